// round 5
// baseline (speedup 1.0000x reference)
#include <cuda_runtime.h>
#include <cuda_fp16.h>
#include <math.h>

#define MAXN 100000
#define MAXE 1600000
typedef unsigned long long u64;

// ---------------- scratch ----------------
__device__ float  g_h  [MAXN * 96];   // conv outputs (layer1 relu'd -> layer2 input, then layer2 out)
__device__ u64    g_fth[MAXN * 32];   // ft packed fp16: [node][lane] = (h0,h1,h2,pad)
__device__ float4 g_el4[MAXN];
__device__ float4 g_er4[MAXN];
__device__ float  g_eec1[MAXE * 3];
__device__ float  g_eec2[MAXE * 3];
__device__ float  g_wc  [MAXE * 3];   // exp weights (CSR order), reused per layer
__device__ int    g_srcc[MAXE];
__device__ int    g_pos [MAXE];
__device__ int    g_deg [MAXN];
__device__ int    g_off [MAXN + 1];
__device__ int    g_woff[MAXN];
__device__ int    g_bsum[128];
__device__ int    g_boff[128];
__device__ float  g_P[MAXN * 10];
__device__ float  g_Q[MAXN * 10];
__device__ float  g_Ve[2][32][3];

__device__ __forceinline__ void ffma2(u64& acc, u64 v, u64 w) {
    asm("fma.rn.f32x2 %0, %1, %2, %0;" : "+l"(acc) : "l"(v), "l"(w));
}
__device__ __forceinline__ float unpack_sum(u64 a) {
    unsigned lo, hi;
    asm("mov.b64 {%0, %1}, %2;" : "=r"(lo), "=r"(hi) : "l"(a));
    return __uint_as_float(lo) + __uint_as_float(hi);
}

// ---------------- K0: fold We @ ae for both layers ----------------
__global__ void k_ve(const float* __restrict__ We1, const float* __restrict__ ae1,
                     const float* __restrict__ We2, const float* __restrict__ ae2) {
    int t = threadIdx.x;
    if (t >= 192) return;
    int c = t / 96, r = t % 96, d = r / 3, h = r % 3;
    const float* We = c ? We2 : We1;
    const float* ae = c ? ae2 : ae1;
    float s = 0.f;
    #pragma unroll
    for (int f = 0; f < 32; f++) s = fmaf(We[d * 96 + h * 32 + f], ae[h * 32 + f], s);
    g_Ve[c][d][h] = s;
}

// ---------------- node transform: 4 nodes/warp, FFMA2 packed along k ----------------
template <int K>
__global__ void k_node4(const float* __restrict__ in,   // nullptr => read g_h
                        const float* __restrict__ W,
                        const float* __restrict__ al, const float* __restrict__ ar,
                        int n) {
    constexpr int KP = K + 2;
    __shared__ float sWT[96 * KP];            // transposed: sWT[c*KP + k]
    __shared__ float sal[96], sar[96];
    for (int idx = threadIdx.x; idx < K * 96; idx += blockDim.x) {
        int k = idx / 96, c = idx % 96;
        sWT[c * KP + k] = W[idx];
    }
    if (threadIdx.x < 96) { sal[threadIdx.x] = al[threadIdx.x]; sar[threadIdx.x] = ar[threadIdx.x]; }
    __syncthreads();

    int warp = (blockIdx.x * blockDim.x + threadIdx.x) >> 5;
    int lane = threadIdx.x & 31;
    int nb = warp * 4;
    if (nb >= n) return;
    const float* base = in ? in : g_h;

    const u64* row[4];
    #pragma unroll
    for (int m = 0; m < 4; m++) {
        int node = nb + m < n ? nb + m : n - 1;
        row[m] = (const u64*)(base + (size_t)node * K);
    }
    const u64* w0p = (const u64*)(sWT + (size_t)lane * KP);
    const u64* w1p = (const u64*)(sWT + (size_t)(lane + 32) * KP);
    const u64* w2p = (const u64*)(sWT + (size_t)(lane + 64) * KP);

    u64 acc[4][3];
    #pragma unroll
    for (int m = 0; m < 4; m++) { acc[m][0] = 0ull; acc[m][1] = 0ull; acc[m][2] = 0ull; }

    #pragma unroll 4
    for (int kp = 0; kp < K / 2; kp++) {
        u64 w0 = w0p[kp], w1 = w1p[kp], w2 = w2p[kp];
        u64 v0 = row[0][kp], v1 = row[1][kp], v2 = row[2][kp], v3 = row[3][kp];
        ffma2(acc[0][0], v0, w0); ffma2(acc[0][1], v0, w1); ffma2(acc[0][2], v0, w2);
        ffma2(acc[1][0], v1, w0); ffma2(acc[1][1], v1, w1); ffma2(acc[1][2], v1, w2);
        ffma2(acc[2][0], v2, w0); ffma2(acc[2][1], v2, w1); ffma2(acc[2][2], v2, w2);
        ffma2(acc[3][0], v3, w0); ffma2(acc[3][1], v3, w1); ffma2(acc[3][2], v3, w2);
    }

    #pragma unroll
    for (int m = 0; m < 4; m++) {
        int node = nb + m;
        if (node >= n) break;
        float a0 = unpack_sum(acc[m][0]);
        float a1 = unpack_sum(acc[m][1]);
        float a2 = unpack_sum(acc[m][2]);
        // packed fp16 ft: one STG.64 per lane
        __half2 p01 = __floats2half2_rn(a0, a1);
        __half2 p2x = __floats2half2_rn(a2, 0.f);
        unsigned plo = *(unsigned*)&p01;
        unsigned phi = *(unsigned*)&p2x;
        g_fth[(size_t)node * 32 + lane] = (u64)plo | ((u64)phi << 32);

        float e0 = a0 * sal[lane], e1 = a1 * sal[lane + 32], e2 = a2 * sal[lane + 64];
        float r0 = a0 * sar[lane], r1 = a1 * sar[lane + 32], r2 = a2 * sar[lane + 64];
        #pragma unroll
        for (int o = 16; o; o >>= 1) {
            e0 += __shfl_xor_sync(0xffffffffu, e0, o);
            e1 += __shfl_xor_sync(0xffffffffu, e1, o);
            e2 += __shfl_xor_sync(0xffffffffu, e2, o);
            r0 += __shfl_xor_sync(0xffffffffu, r0, o);
            r1 += __shfl_xor_sync(0xffffffffu, r1, o);
            r2 += __shfl_xor_sync(0xffffffffu, r2, o);
        }
        if (lane == 0) {
            g_el4[node] = make_float4(e0, e1, e2, 0.f);
            g_er4[node] = make_float4(r0, r1, r2, 0.f);
        }
    }
}

// ---------------- ee for both layers, written directly in CSR order ----------------
__global__ void k_ee(const float* __restrict__ ef, int e_cnt) {
    __shared__ float sVe[192];
    if (threadIdx.x < 192) sVe[threadIdx.x] = ((const float*)g_Ve)[threadIdx.x];
    __syncthreads();
    int e = blockIdx.x * blockDim.x + threadIdx.x;
    if (e >= e_cnt) return;
    const float4* p = (const float4*)(ef + (size_t)e * 32);
    float acc0 = 0, acc1 = 0, acc2 = 0, acc3 = 0, acc4 = 0, acc5 = 0;
    #pragma unroll
    for (int q = 0; q < 8; q++) {
        float4 v = p[q];
        float xs[4] = {v.x, v.y, v.z, v.w};
        #pragma unroll
        for (int j = 0; j < 4; j++) {
            int d = q * 4 + j;
            float x = xs[j];
            acc0 = fmaf(x, sVe[d * 3 + 0],      acc0);
            acc1 = fmaf(x, sVe[d * 3 + 1],      acc1);
            acc2 = fmaf(x, sVe[d * 3 + 2],      acc2);
            acc3 = fmaf(x, sVe[96 + d * 3 + 0], acc3);
            acc4 = fmaf(x, sVe[96 + d * 3 + 1], acc4);
            acc5 = fmaf(x, sVe[96 + d * 3 + 2], acc5);
        }
    }
    size_t pp = (size_t)g_pos[e] * 3;
    g_eec1[pp + 0] = acc0; g_eec1[pp + 1] = acc1; g_eec1[pp + 2] = acc2;
    g_eec2[pp + 0] = acc3; g_eec2[pp + 1] = acc4; g_eec2[pp + 2] = acc5;
}

// ---------------- CSR build ----------------
__global__ void k_zero_deg(int n) {
    int i = blockIdx.x * blockDim.x + threadIdx.x;
    if (i < n) g_deg[i] = 0;
}
__global__ void k_deg(const int* __restrict__ dst, int e) {
    int i = blockIdx.x * blockDim.x + threadIdx.x;
    if (i < e) atomicAdd(&g_deg[dst[i]], 1);
}
__global__ void k_scan1(int n) {
    __shared__ int s[1024];
    int idx = blockIdx.x * 1024 + threadIdx.x;
    int v = (idx < n) ? g_deg[idx] : 0;
    s[threadIdx.x] = v;
    __syncthreads();
    #pragma unroll
    for (int off = 1; off < 1024; off <<= 1) {
        int t = (threadIdx.x >= off) ? s[threadIdx.x - off] : 0;
        __syncthreads();
        s[threadIdx.x] += t;
        __syncthreads();
    }
    if (idx < n) g_off[idx] = s[threadIdx.x] - v;
    if (threadIdx.x == 1023) g_bsum[blockIdx.x] = s[1023];
}
__global__ void k_scan2(int nb) {
    __shared__ int s[128];
    int tid = threadIdx.x;
    int v = (tid < nb) ? g_bsum[tid] : 0;
    s[tid] = v;
    __syncthreads();
    #pragma unroll
    for (int off = 1; off < 128; off <<= 1) {
        int t = (tid >= off) ? s[tid - off] : 0;
        __syncthreads();
        s[tid] += t;
        __syncthreads();
    }
    if (tid < nb) g_boff[tid] = s[tid] - v;
}
__global__ void k_scan3(int n, int e) {
    int idx = blockIdx.x * 1024 + threadIdx.x;
    if (idx < n) {
        int o = g_off[idx] + g_boff[blockIdx.x];
        g_off[idx] = o;
        g_woff[idx] = o;
    }
    if (idx == 0) g_off[n] = e;
}
__global__ void k_scatter(const int* __restrict__ src, const int* __restrict__ dst, int e) {
    int i = blockIdx.x * blockDim.x + threadIdx.x;
    if (i < e) {
        int p = atomicAdd(&g_woff[dst[i]], 1);
        g_srcc[p] = src[i];
        g_pos[i] = p;
    }
}

// ---------------- fused conv: 2-phase; phase2 gathers packed fp16 ft (LDG.64) ------
__global__ void k_conv(const float* __restrict__ bias, int which_ee, int n, int do_relu) {
    int gw   = (blockIdx.x * blockDim.x + threadIdx.x) >> 5;
    int lane = threadIdx.x & 31;
    if (gw >= n) return;
    const float* __restrict__ eec = which_ee ? g_eec2 : g_eec1;
    int beg = g_off[gw], end = g_off[gw + 1];
    float b0 = bias[lane], b1 = bias[lane + 32], b2 = bias[lane + 64];
    float out0, out1, out2;
    if (beg == end) {
        out0 = b0; out1 = b1; out2 = b2;
    } else {
        float4 er = g_er4[gw];
        // phase 1: edge-parallel logits -> exp -> store + per-lane sum
        float s0 = 0.f, s1 = 0.f, s2 = 0.f;
        for (int i = beg + lane; i < end; i += 32) {
            int sn = g_srcc[i];
            float4 el = g_el4[sn];
            size_t ip = (size_t)i * 3;
            float w0 = el.x + er.x + eec[ip + 0];
            float w1 = el.y + er.y + eec[ip + 1];
            float w2 = el.z + er.z + eec[ip + 2];
            w0 = (w0 > 0.f) ? w0 : 0.2f * w0;
            w1 = (w1 > 0.f) ? w1 : 0.2f * w1;
            w2 = (w2 > 0.f) ? w2 : 0.2f * w2;
            float x0 = __expf(w0), x1 = __expf(w1), x2 = __expf(w2);
            g_wc[ip + 0] = x0; g_wc[ip + 1] = x1; g_wc[ip + 2] = x2;
            s0 += x0; s1 += x1; s2 += x2;
        }
        #pragma unroll
        for (int o = 16; o; o >>= 1) {
            s0 += __shfl_xor_sync(0xffffffffu, s0, o);
            s1 += __shfl_xor_sync(0xffffffffu, s1, o);
            s2 += __shfl_xor_sync(0xffffffffu, s2, o);
        }
        __syncwarp();
        // phase 2: feature-parallel aggregation; one LDG.64 fp16 gather per edge
        float a0 = 0.f, a1 = 0.f, a2 = 0.f;
        #pragma unroll 4
        for (int i = beg; i < end; i++) {
            int sn = g_srcc[i];
            size_t ip = (size_t)i * 3;
            float x0 = g_wc[ip + 0], x1 = g_wc[ip + 1], x2 = g_wc[ip + 2];
            u64 v = g_fth[(size_t)sn * 32 + lane];
            unsigned lo = (unsigned)v, hi = (unsigned)(v >> 32);
            __half2 p01 = *(__half2*)&lo;
            __half2 p2x = *(__half2*)&hi;
            float2 f01 = __half22float2(p01);
            float  f2  = __low2float(p2x);
            a0 = fmaf(x0, f01.x, a0);
            a1 = fmaf(x1, f01.y, a1);
            a2 = fmaf(x2, f2,    a2);
        }
        out0 = a0 / s0 + b0;
        out1 = a1 / s1 + b1;
        out2 = a2 / s2 + b2;
    }
    if (do_relu) {
        out0 = fmaxf(out0, 0.f); out1 = fmaxf(out1, 0.f); out2 = fmaxf(out2, 0.f);
    }
    float* o = g_h + (size_t)gw * 96;
    o[lane] = out0; o[lane + 32] = out1; o[lane + 64] = out2;
}

// ---------------- per-node P = h@Wp_top, Q = h@Wp_bot + bp ----------------
__global__ void k_pq(const float* __restrict__ Wp, const float* __restrict__ bp, int n) {
    __shared__ float sW[1920];
    __shared__ float sb[10];
    for (int i = threadIdx.x; i < 1920; i += blockDim.x) sW[i] = Wp[i];
    if (threadIdx.x < 10) sb[threadIdx.x] = bp[threadIdx.x];
    __syncthreads();
    int t = blockIdx.x * blockDim.x + threadIdx.x;
    if (t >= n * 10) return;
    int node = t / 10, c = t % 10;
    const float* hr = g_h + (size_t)node * 96;
    float p = 0.f, q = 0.f;
    #pragma unroll 4
    for (int j = 0; j < 96; j++) {
        float hv = hr[j];
        p = fmaf(hv, sW[j * 10 + c], p);
        q = fmaf(hv, sW[(96 + j) * 10 + c], q);
    }
    g_P[t] = p;
    g_Q[t] = q + sb[c];
}

// ---------------- score[e,:] = P[src] + Q[dst] ----------------
__global__ void k_score(const int* __restrict__ src, const int* __restrict__ dst,
                        float* __restrict__ out, int e) {
    __shared__ float sm[2560];
    int tid = threadIdx.x;
    int eb = blockIdx.x * 256;
    int ed = eb + tid;
    if (ed < e) {
        int sn = src[ed], dn = dst[ed];
        #pragma unroll
        for (int c = 0; c < 10; c++)
            sm[tid * 10 + c] = g_P[sn * 10 + c] + g_Q[dn * 10 + c];
    }
    __syncthreads();
    int cnt = (e - eb < 256 ? e - eb : 256) * 10;
    for (int i = tid; i < cnt; i += 256)
        out[(size_t)eb * 10 + i] = sm[i];
}

// ---------------- driver ----------------
extern "C" void kernel_launch(void* const* d_in, const int* in_sizes, int n_in,
                              void* d_out, int out_size) {
    const float* nfeats = (const float*)d_in[0];
    const float* efeats = (const float*)d_in[1];
    const int*   src    = (const int*)  d_in[2];
    const int*   dst    = (const int*)  d_in[3];
    const float* W1  = (const float*)d_in[4];
    const float* We1 = (const float*)d_in[5];
    const float* al1 = (const float*)d_in[6];
    const float* ar1 = (const float*)d_in[7];
    const float* ae1 = (const float*)d_in[8];
    const float* b1  = (const float*)d_in[9];
    const float* W2  = (const float*)d_in[10];
    const float* We2 = (const float*)d_in[11];
    const float* al2 = (const float*)d_in[12];
    const float* ar2 = (const float*)d_in[13];
    const float* ae2 = (const float*)d_in[14];
    const float* b2  = (const float*)d_in[15];
    const float* Wp  = (const float*)d_in[16];
    const float* bp  = (const float*)d_in[17];
    float* out = (float*)d_out;

    int n = in_sizes[0] / 64;   // 100000
    int e = in_sizes[2];        // 1600000

    int eb   = (e + 255) / 256;
    int nb   = (n + 255) / 256;
    int nwb  = (n + 7) / 8;
    int nwb4 = (n + 31) / 32;
    int nb1k = (n + 1023) / 1024;

    // (profiled slot = launch idx 3 -> k_node4<64>)
    k_zero_deg<<<nb, 256>>>(n);
    k_deg<<<eb, 256>>>(dst, e);
    k_ve<<<1, 192>>>(We1, ae1, We2, ae2);
    k_node4<64><<<nwb4, 256>>>(nfeats, W1, al1, ar1, n);

    k_scan1<<<nb1k, 1024>>>(n);
    k_scan2<<<1, 128>>>(nb1k);
    k_scan3<<<nb1k, 1024>>>(n, e);
    k_scatter<<<eb, 256>>>(src, dst, e);
    k_ee<<<eb, 256>>>(efeats, e);

    // layer 1
    k_conv<<<nwb, 256>>>(b1, 0, n, 1);

    // layer 2
    k_node4<96><<<nwb4, 256>>>(nullptr, W2, al2, ar2, n);
    k_conv<<<nwb, 256>>>(b2, 1, n, 0);

    // edge score head
    k_pq<<<(n * 10 + 255) / 256, 256>>>(Wp, bp, n);
    k_score<<<eb, 256>>>(src, dst, out, e);
}

// round 6
// speedup vs baseline: 1.3356x; 1.3356x over previous
#include <cuda_runtime.h>
#include <math.h>

#define MAXN 100000
#define MAXE 1600000
typedef unsigned long long u64;

// ---------------- scratch ----------------
__device__ float  g_ft[MAXN * 96];
__device__ float  g_h [MAXN * 96];
__device__ float4 g_el4[MAXN];
__device__ float4 g_er4[MAXN];
__device__ float  g_eec1[MAXE * 3];
__device__ float  g_eec2[MAXE * 3];
__device__ int    g_srcc[MAXE];
__device__ int    g_pos [MAXE];
__device__ int    g_deg [MAXN];
__device__ int    g_off [MAXN + 1];
__device__ int    g_woff[MAXN];
__device__ int    g_bsum[128];
__device__ int    g_boff[128];
__device__ float  g_P[MAXN * 10];
__device__ float  g_Q[MAXN * 10];
__device__ float  g_Ve[2][32][3];

__device__ __forceinline__ void ffma2(u64& acc, u64 v, u64 w) {
    asm("fma.rn.f32x2 %0, %1, %2, %0;" : "+l"(acc) : "l"(v), "l"(w));
}
__device__ __forceinline__ float unpack_sum(u64 a) {
    unsigned lo, hi;
    asm("mov.b64 {%0, %1}, %2;" : "=r"(lo), "=r"(hi) : "l"(a));
    return __uint_as_float(lo) + __uint_as_float(hi);
}

// ---------------- K0: fold We @ ae for both layers ----------------
__global__ void k_ve(const float* __restrict__ We1, const float* __restrict__ ae1,
                     const float* __restrict__ We2, const float* __restrict__ ae2) {
    int t = threadIdx.x;
    if (t >= 192) return;
    int c = t / 96, r = t % 96, d = r / 3, h = r % 3;
    const float* We = c ? We2 : We1;
    const float* ae = c ? ae2 : ae1;
    float s = 0.f;
    #pragma unroll
    for (int f = 0; f < 32; f++) s = fmaf(We[d * 96 + h * 32 + f], ae[h * 32 + f], s);
    g_Ve[c][d][h] = s;
}

// ---------------- node transform: 4 nodes/warp, FFMA2 packed along k (R3-exact) ----
template <int K>
__global__ void k_node4(const float* __restrict__ in,   // nullptr => read g_h
                        const float* __restrict__ W,
                        const float* __restrict__ al, const float* __restrict__ ar,
                        int n) {
    constexpr int KP = K + 2;
    __shared__ float sWT[96 * KP];
    __shared__ float sal[96], sar[96];
    for (int idx = threadIdx.x; idx < K * 96; idx += blockDim.x) {
        int k = idx / 96, c = idx % 96;
        sWT[c * KP + k] = W[idx];
    }
    if (threadIdx.x < 96) { sal[threadIdx.x] = al[threadIdx.x]; sar[threadIdx.x] = ar[threadIdx.x]; }
    __syncthreads();

    int warp = (blockIdx.x * blockDim.x + threadIdx.x) >> 5;
    int lane = threadIdx.x & 31;
    int nb = warp * 4;
    if (nb >= n) return;
    const float* base = in ? in : g_h;

    const u64* row[4];
    #pragma unroll
    for (int m = 0; m < 4; m++) {
        int node = nb + m < n ? nb + m : n - 1;
        row[m] = (const u64*)(base + (size_t)node * K);
    }
    const u64* w0p = (const u64*)(sWT + (size_t)lane * KP);
    const u64* w1p = (const u64*)(sWT + (size_t)(lane + 32) * KP);
    const u64* w2p = (const u64*)(sWT + (size_t)(lane + 64) * KP);

    u64 acc[4][3];
    #pragma unroll
    for (int m = 0; m < 4; m++) { acc[m][0] = 0ull; acc[m][1] = 0ull; acc[m][2] = 0ull; }

    #pragma unroll 4
    for (int kp = 0; kp < K / 2; kp++) {
        u64 w0 = w0p[kp], w1 = w1p[kp], w2 = w2p[kp];
        u64 v0 = row[0][kp], v1 = row[1][kp], v2 = row[2][kp], v3 = row[3][kp];
        ffma2(acc[0][0], v0, w0); ffma2(acc[0][1], v0, w1); ffma2(acc[0][2], v0, w2);
        ffma2(acc[1][0], v1, w0); ffma2(acc[1][1], v1, w1); ffma2(acc[1][2], v1, w2);
        ffma2(acc[2][0], v2, w0); ffma2(acc[2][1], v2, w1); ffma2(acc[2][2], v2, w2);
        ffma2(acc[3][0], v3, w0); ffma2(acc[3][1], v3, w1); ffma2(acc[3][2], v3, w2);
    }

    #pragma unroll
    for (int m = 0; m < 4; m++) {
        int node = nb + m;
        if (node >= n) break;
        float a0 = unpack_sum(acc[m][0]);
        float a1 = unpack_sum(acc[m][1]);
        float a2 = unpack_sum(acc[m][2]);
        float* fo = g_ft + (size_t)node * 96;
        fo[lane] = a0; fo[lane + 32] = a1; fo[lane + 64] = a2;
        float e0 = a0 * sal[lane], e1 = a1 * sal[lane + 32], e2 = a2 * sal[lane + 64];
        float r0 = a0 * sar[lane], r1 = a1 * sar[lane + 32], r2 = a2 * sar[lane + 64];
        #pragma unroll
        for (int o = 16; o; o >>= 1) {
            e0 += __shfl_xor_sync(0xffffffffu, e0, o);
            e1 += __shfl_xor_sync(0xffffffffu, e1, o);
            e2 += __shfl_xor_sync(0xffffffffu, e2, o);
            r0 += __shfl_xor_sync(0xffffffffu, r0, o);
            r1 += __shfl_xor_sync(0xffffffffu, r1, o);
            r2 += __shfl_xor_sync(0xffffffffu, r2, o);
        }
        if (lane == 0) {
            g_el4[node] = make_float4(e0, e1, e2, 0.f);
            g_er4[node] = make_float4(r0, r1, r2, 0.f);
        }
    }
}

// ---------------- ee for both layers, written directly in CSR order ----------------
__global__ void k_ee(const float* __restrict__ ef, int e_cnt) {
    __shared__ float sVe[192];
    if (threadIdx.x < 192) sVe[threadIdx.x] = ((const float*)g_Ve)[threadIdx.x];
    __syncthreads();
    int e = blockIdx.x * blockDim.x + threadIdx.x;
    if (e >= e_cnt) return;
    const float4* p = (const float4*)(ef + (size_t)e * 32);
    float acc0 = 0, acc1 = 0, acc2 = 0, acc3 = 0, acc4 = 0, acc5 = 0;
    #pragma unroll
    for (int q = 0; q < 8; q++) {
        float4 v = p[q];
        float xs[4] = {v.x, v.y, v.z, v.w};
        #pragma unroll
        for (int j = 0; j < 4; j++) {
            int d = q * 4 + j;
            float x = xs[j];
            acc0 = fmaf(x, sVe[d * 3 + 0],      acc0);
            acc1 = fmaf(x, sVe[d * 3 + 1],      acc1);
            acc2 = fmaf(x, sVe[d * 3 + 2],      acc2);
            acc3 = fmaf(x, sVe[96 + d * 3 + 0], acc3);
            acc4 = fmaf(x, sVe[96 + d * 3 + 1], acc4);
            acc5 = fmaf(x, sVe[96 + d * 3 + 2], acc5);
        }
    }
    size_t pp = (size_t)g_pos[e] * 3;
    g_eec1[pp + 0] = acc0; g_eec1[pp + 1] = acc1; g_eec1[pp + 2] = acc2;
    g_eec2[pp + 0] = acc3; g_eec2[pp + 1] = acc4; g_eec2[pp + 2] = acc5;
}

// ---------------- CSR build ----------------
__global__ void k_zero_deg(int n) {
    int i = blockIdx.x * blockDim.x + threadIdx.x;
    if (i < n) g_deg[i] = 0;
}
__global__ void k_deg(const int* __restrict__ dst, int e) {
    int i = blockIdx.x * blockDim.x + threadIdx.x;
    if (i < e) atomicAdd(&g_deg[dst[i]], 1);
}
__global__ void k_scan1(int n) {
    __shared__ int s[1024];
    int idx = blockIdx.x * 1024 + threadIdx.x;
    int v = (idx < n) ? g_deg[idx] : 0;
    s[threadIdx.x] = v;
    __syncthreads();
    #pragma unroll
    for (int off = 1; off < 1024; off <<= 1) {
        int t = (threadIdx.x >= off) ? s[threadIdx.x - off] : 0;
        __syncthreads();
        s[threadIdx.x] += t;
        __syncthreads();
    }
    if (idx < n) g_off[idx] = s[threadIdx.x] - v;
    if (threadIdx.x == 1023) g_bsum[blockIdx.x] = s[1023];
}
__global__ void k_scan2(int nb) {
    __shared__ int s[128];
    int tid = threadIdx.x;
    int v = (tid < nb) ? g_bsum[tid] : 0;
    s[tid] = v;
    __syncthreads();
    #pragma unroll
    for (int off = 1; off < 128; off <<= 1) {
        int t = (tid >= off) ? s[tid - off] : 0;
        __syncthreads();
        s[tid] += t;
        __syncthreads();
    }
    if (tid < nb) g_boff[tid] = s[tid] - v;
}
__global__ void k_scan3(int n, int e) {
    int idx = blockIdx.x * 1024 + threadIdx.x;
    if (idx < n) {
        int o = g_off[idx] + g_boff[blockIdx.x];
        g_off[idx] = o;
        g_woff[idx] = o;
    }
    if (idx == 0) g_off[n] = e;
}
__global__ void k_scatter(const int* __restrict__ src, const int* __restrict__ dst, int e) {
    int i = blockIdx.x * blockDim.x + threadIdx.x;
    if (i < e) {
        int p = atomicAdd(&g_woff[dst[i]], 1);
        g_srcc[p] = src[i];
        g_pos[i] = p;
    }
}

// ---------------- fused conv: chunked, smem-staged exp weights (no g_wc) ----------
// One warp per dst node; 32-edge chunks. Phase A (lane-parallel): logits->exp into
// smem + src id. Phase B (feature-parallel): LDS broadcasts + 3 independent LDGs/edge.
__global__ void k_conv(const float* __restrict__ bias, int which_ee, int n, int do_relu) {
    __shared__ float swc[8][3][32];
    __shared__ int   ssn[8][32];
    int wib  = threadIdx.x >> 5;                    // warp in block
    int gw   = (blockIdx.x * blockDim.x + threadIdx.x) >> 5;
    int lane = threadIdx.x & 31;
    if (gw >= n) return;
    const float* __restrict__ eec = which_ee ? g_eec2 : g_eec1;
    int beg = g_off[gw], end = g_off[gw + 1];
    float b0 = bias[lane], b1 = bias[lane + 32], b2 = bias[lane + 64];
    float out0, out1, out2;
    if (beg == end) {
        out0 = b0; out1 = b1; out2 = b2;
    } else {
        float4 er = g_er4[gw];
        float s0 = 0.f, s1 = 0.f, s2 = 0.f;
        float a0 = 0.f, a1 = 0.f, a2 = 0.f;
        for (int chunk = beg; chunk < end; chunk += 32) {
            int cnt = end - chunk; if (cnt > 32) cnt = 32;
            // phase A
            float x0 = 0.f, x1 = 0.f, x2 = 0.f;
            if (lane < cnt) {
                int i = chunk + lane;
                int sn = g_srcc[i];
                ssn[wib][lane] = sn;
                float4 el = g_el4[sn];
                size_t ip = (size_t)i * 3;
                float w0 = el.x + er.x + eec[ip + 0];
                float w1 = el.y + er.y + eec[ip + 1];
                float w2 = el.z + er.z + eec[ip + 2];
                w0 = (w0 > 0.f) ? w0 : 0.2f * w0;
                w1 = (w1 > 0.f) ? w1 : 0.2f * w1;
                w2 = (w2 > 0.f) ? w2 : 0.2f * w2;
                x0 = __expf(w0); x1 = __expf(w1); x2 = __expf(w2);
                swc[wib][0][lane] = x0;
                swc[wib][1][lane] = x1;
                swc[wib][2][lane] = x2;
            }
            s0 += x0; s1 += x1; s2 += x2;
            __syncwarp();
            // phase B: feature-parallel; 3 independent LDGs per edge, unroll for MLP
            #pragma unroll 4
            for (int j = 0; j < cnt; j++) {
                int   sn = ssn[wib][j];
                float y0 = swc[wib][0][j];
                float y1 = swc[wib][1][j];
                float y2 = swc[wib][2][j];
                const float* fr = g_ft + (size_t)sn * 96;
                a0 = fmaf(y0, fr[lane],      a0);
                a1 = fmaf(y1, fr[lane + 32], a1);
                a2 = fmaf(y2, fr[lane + 64], a2);
            }
            __syncwarp();
        }
        #pragma unroll
        for (int o = 16; o; o >>= 1) {
            s0 += __shfl_xor_sync(0xffffffffu, s0, o);
            s1 += __shfl_xor_sync(0xffffffffu, s1, o);
            s2 += __shfl_xor_sync(0xffffffffu, s2, o);
        }
        out0 = a0 / s0 + b0;
        out1 = a1 / s1 + b1;
        out2 = a2 / s2 + b2;
    }
    if (do_relu) {
        out0 = fmaxf(out0, 0.f); out1 = fmaxf(out1, 0.f); out2 = fmaxf(out2, 0.f);
    }
    float* o = g_h + (size_t)gw * 96;
    o[lane] = out0; o[lane + 32] = out1; o[lane + 64] = out2;
}

// ---------------- per-node P = h@Wp_top, Q = h@Wp_bot + bp ----------------
__global__ void k_pq(const float* __restrict__ Wp, const float* __restrict__ bp, int n) {
    __shared__ float sW[1920];
    __shared__ float sb[10];
    for (int i = threadIdx.x; i < 1920; i += blockDim.x) sW[i] = Wp[i];
    if (threadIdx.x < 10) sb[threadIdx.x] = bp[threadIdx.x];
    __syncthreads();
    int t = blockIdx.x * blockDim.x + threadIdx.x;
    if (t >= n * 10) return;
    int node = t / 10, c = t % 10;
    const float* hr = g_h + (size_t)node * 96;
    float p = 0.f, q = 0.f;
    #pragma unroll 4
    for (int j = 0; j < 96; j++) {
        float hv = hr[j];
        p = fmaf(hv, sW[j * 10 + c], p);
        q = fmaf(hv, sW[(96 + j) * 10 + c], q);
    }
    g_P[t] = p;
    g_Q[t] = q + sb[c];
}

// ---------------- score[e,:] = P[src] + Q[dst] ----------------
__global__ void k_score(const int* __restrict__ src, const int* __restrict__ dst,
                        float* __restrict__ out, int e) {
    __shared__ float sm[2560];
    int tid = threadIdx.x;
    int eb = blockIdx.x * 256;
    int ed = eb + tid;
    if (ed < e) {
        int sn = src[ed], dn = dst[ed];
        #pragma unroll
        for (int c = 0; c < 10; c++)
            sm[tid * 10 + c] = g_P[sn * 10 + c] + g_Q[dn * 10 + c];
    }
    __syncthreads();
    int cnt = (e - eb < 256 ? e - eb : 256) * 10;
    for (int i = tid; i < cnt; i += 256)
        out[(size_t)eb * 10 + i] = sm[i];
}

// ---------------- driver ----------------
extern "C" void kernel_launch(void* const* d_in, const int* in_sizes, int n_in,
                              void* d_out, int out_size) {
    const float* nfeats = (const float*)d_in[0];
    const float* efeats = (const float*)d_in[1];
    const int*   src    = (const int*)  d_in[2];
    const int*   dst    = (const int*)  d_in[3];
    const float* W1  = (const float*)d_in[4];
    const float* We1 = (const float*)d_in[5];
    const float* al1 = (const float*)d_in[6];
    const float* ar1 = (const float*)d_in[7];
    const float* ae1 = (const float*)d_in[8];
    const float* b1  = (const float*)d_in[9];
    const float* W2  = (const float*)d_in[10];
    const float* We2 = (const float*)d_in[11];
    const float* al2 = (const float*)d_in[12];
    const float* ar2 = (const float*)d_in[13];
    const float* ae2 = (const float*)d_in[14];
    const float* b2  = (const float*)d_in[15];
    const float* Wp  = (const float*)d_in[16];
    const float* bp  = (const float*)d_in[17];
    float* out = (float*)d_out;

    int n = in_sizes[0] / 64;   // 100000
    int e = in_sizes[2];        // 1600000

    int eb   = (e + 255) / 256;
    int nb   = (n + 255) / 256;
    int nwb  = (n + 7) / 8;
    int nwb4 = (n + 31) / 32;
    int nb1k = (n + 1023) / 1024;

    // (profiled slot = launch idx 3 -> k_node4<64>)
    k_zero_deg<<<nb, 256>>>(n);
    k_deg<<<eb, 256>>>(dst, e);
    k_ve<<<1, 192>>>(We1, ae1, We2, ae2);
    k_node4<64><<<nwb4, 256>>>(nfeats, W1, al1, ar1, n);

    k_scan1<<<nb1k, 1024>>>(n);
    k_scan2<<<1, 128>>>(nb1k);
    k_scan3<<<nb1k, 1024>>>(n, e);
    k_scatter<<<eb, 256>>>(src, dst, e);
    k_ee<<<eb, 256>>>(efeats, e);

    // layer 1
    k_conv<<<nwb, 256>>>(b1, 0, n, 1);

    // layer 2
    k_node4<96><<<nwb4, 256>>>(nullptr, W2, al2, ar2, n);
    k_conv<<<nwb, 256>>>(b2, 1, n, 0);

    // edge score head
    k_pq<<<(n * 10 + 255) / 256, 256>>>(Wp, bp, n);
    k_score<<<eb, 256>>>(src, dst, out, e);
}

// round 7
// speedup vs baseline: 1.4728x; 1.1028x over previous
#include <cuda_runtime.h>
#include <math.h>

#define MAXN 100000
#define MAXE 1600000
typedef unsigned long long u64;

// ---------------- scratch ----------------
__device__ float  g_ft[MAXN * 96];
__device__ float  g_h [MAXN * 96];
__device__ float4 g_el4[MAXN];
__device__ float4 g_er4[MAXN];
__device__ float  g_eec1[MAXE * 3];
__device__ float  g_eec2[MAXE * 3];
__device__ float  g_wc  [MAXE * 3];
__device__ int    g_srcc[MAXE];
__device__ int    g_pos [MAXE];
__device__ int    g_deg [MAXN];
__device__ int    g_off [MAXN + 1];
__device__ int    g_woff[MAXN];
__device__ int    g_bsum[128];
__device__ int    g_boff[128];
__device__ float  g_P[MAXN * 10];
__device__ float  g_Q[MAXN * 10];
__device__ float  g_Ve[2][32][3];

__device__ __forceinline__ void ffma2(u64& acc, u64 v, u64 w) {
    asm("fma.rn.f32x2 %0, %1, %2, %0;" : "+l"(acc) : "l"(v), "l"(w));
}
__device__ __forceinline__ float unpack_sum(u64 a) {
    unsigned lo, hi;
    asm("mov.b64 {%0, %1}, %2;" : "=r"(lo), "=r"(hi) : "l"(a));
    return __uint_as_float(lo) + __uint_as_float(hi);
}

// ---------------- K0: fold We @ ae for both layers ----------------
__global__ void k_ve(const float* __restrict__ We1, const float* __restrict__ ae1,
                     const float* __restrict__ We2, const float* __restrict__ ae2) {
    int t = threadIdx.x;
    if (t >= 192) return;
    int c = t / 96, r = t % 96, d = r / 3, h = r % 3;
    const float* We = c ? We2 : We1;
    const float* ae = c ? ae2 : ae1;
    float s = 0.f;
    #pragma unroll
    for (int f = 0; f < 32; f++) s = fmaf(We[d * 96 + h * 32 + f], ae[h * 32 + f], s);
    g_Ve[c][d][h] = s;
}

// ---------------- node transform: 4 nodes/warp, FFMA2 packed along k ----------------
template <int K>
__global__ void k_node4(const float* __restrict__ in,   // nullptr => read g_h
                        const float* __restrict__ W,
                        const float* __restrict__ al, const float* __restrict__ ar,
                        int n) {
    constexpr int KP = K + 2;
    __shared__ float sWT[96 * KP];
    __shared__ float sal[96], sar[96];
    for (int idx = threadIdx.x; idx < K * 96; idx += blockDim.x) {
        int k = idx / 96, c = idx % 96;
        sWT[c * KP + k] = W[idx];
    }
    if (threadIdx.x < 96) { sal[threadIdx.x] = al[threadIdx.x]; sar[threadIdx.x] = ar[threadIdx.x]; }
    __syncthreads();

    int warp = (blockIdx.x * blockDim.x + threadIdx.x) >> 5;
    int lane = threadIdx.x & 31;
    int nb = warp * 4;
    if (nb >= n) return;
    const float* base = in ? in : g_h;

    const u64* row[4];
    #pragma unroll
    for (int m = 0; m < 4; m++) {
        int node = nb + m < n ? nb + m : n - 1;
        row[m] = (const u64*)(base + (size_t)node * K);
    }
    const u64* w0p = (const u64*)(sWT + (size_t)lane * KP);
    const u64* w1p = (const u64*)(sWT + (size_t)(lane + 32) * KP);
    const u64* w2p = (const u64*)(sWT + (size_t)(lane + 64) * KP);

    u64 acc[4][3];
    #pragma unroll
    for (int m = 0; m < 4; m++) { acc[m][0] = 0ull; acc[m][1] = 0ull; acc[m][2] = 0ull; }

    #pragma unroll 4
    for (int kp = 0; kp < K / 2; kp++) {
        u64 w0 = w0p[kp], w1 = w1p[kp], w2 = w2p[kp];
        u64 v0 = row[0][kp], v1 = row[1][kp], v2 = row[2][kp], v3 = row[3][kp];
        ffma2(acc[0][0], v0, w0); ffma2(acc[0][1], v0, w1); ffma2(acc[0][2], v0, w2);
        ffma2(acc[1][0], v1, w0); ffma2(acc[1][1], v1, w1); ffma2(acc[1][2], v1, w2);
        ffma2(acc[2][0], v2, w0); ffma2(acc[2][1], v2, w1); ffma2(acc[2][2], v2, w2);
        ffma2(acc[3][0], v3, w0); ffma2(acc[3][1], v3, w1); ffma2(acc[3][2], v3, w2);
    }

    #pragma unroll
    for (int m = 0; m < 4; m++) {
        int node = nb + m;
        if (node >= n) break;
        float a0 = unpack_sum(acc[m][0]);
        float a1 = unpack_sum(acc[m][1]);
        float a2 = unpack_sum(acc[m][2]);
        float* fo = g_ft + (size_t)node * 96;
        fo[lane] = a0; fo[lane + 32] = a1; fo[lane + 64] = a2;
        float e0 = a0 * sal[lane], e1 = a1 * sal[lane + 32], e2 = a2 * sal[lane + 64];
        float r0 = a0 * sar[lane], r1 = a1 * sar[lane + 32], r2 = a2 * sar[lane + 64];
        #pragma unroll
        for (int o = 16; o; o >>= 1) {
            e0 += __shfl_xor_sync(0xffffffffu, e0, o);
            e1 += __shfl_xor_sync(0xffffffffu, e1, o);
            e2 += __shfl_xor_sync(0xffffffffu, e2, o);
            r0 += __shfl_xor_sync(0xffffffffu, r0, o);
            r1 += __shfl_xor_sync(0xffffffffu, r1, o);
            r2 += __shfl_xor_sync(0xffffffffu, r2, o);
        }
        if (lane == 0) {
            g_el4[node] = make_float4(e0, e1, e2, 0.f);
            g_er4[node] = make_float4(r0, r1, r2, 0.f);
        }
    }
}

// ---------------- ee for both layers, written directly in CSR order ----------------
__global__ void k_ee(const float* __restrict__ ef, int e_cnt) {
    __shared__ float sVe[192];
    if (threadIdx.x < 192) sVe[threadIdx.x] = ((const float*)g_Ve)[threadIdx.x];
    __syncthreads();
    int e = blockIdx.x * blockDim.x + threadIdx.x;
    if (e >= e_cnt) return;
    const float4* p = (const float4*)(ef + (size_t)e * 32);
    float acc0 = 0, acc1 = 0, acc2 = 0, acc3 = 0, acc4 = 0, acc5 = 0;
    #pragma unroll
    for (int q = 0; q < 8; q++) {
        float4 v = p[q];
        float xs[4] = {v.x, v.y, v.z, v.w};
        #pragma unroll
        for (int j = 0; j < 4; j++) {
            int d = q * 4 + j;
            float x = xs[j];
            acc0 = fmaf(x, sVe[d * 3 + 0],      acc0);
            acc1 = fmaf(x, sVe[d * 3 + 1],      acc1);
            acc2 = fmaf(x, sVe[d * 3 + 2],      acc2);
            acc3 = fmaf(x, sVe[96 + d * 3 + 0], acc3);
            acc4 = fmaf(x, sVe[96 + d * 3 + 1], acc4);
            acc5 = fmaf(x, sVe[96 + d * 3 + 2], acc5);
        }
    }
    size_t pp = (size_t)g_pos[e] * 3;
    g_eec1[pp + 0] = acc0; g_eec1[pp + 1] = acc1; g_eec1[pp + 2] = acc2;
    g_eec2[pp + 0] = acc3; g_eec2[pp + 1] = acc4; g_eec2[pp + 2] = acc5;
}

// ---------------- CSR build ----------------
__global__ void k_zero_deg(int n) {
    int i = blockIdx.x * blockDim.x + threadIdx.x;
    if (i < n) g_deg[i] = 0;
}
__global__ void k_deg(const int* __restrict__ dst, int e) {
    int i = blockIdx.x * blockDim.x + threadIdx.x;
    if (i < e) atomicAdd(&g_deg[dst[i]], 1);
}
__global__ void k_scan1(int n) {
    __shared__ int s[1024];
    int idx = blockIdx.x * 1024 + threadIdx.x;
    int v = (idx < n) ? g_deg[idx] : 0;
    s[threadIdx.x] = v;
    __syncthreads();
    #pragma unroll
    for (int off = 1; off < 1024; off <<= 1) {
        int t = (threadIdx.x >= off) ? s[threadIdx.x - off] : 0;
        __syncthreads();
        s[threadIdx.x] += t;
        __syncthreads();
    }
    if (idx < n) g_off[idx] = s[threadIdx.x] - v;
    if (threadIdx.x == 1023) g_bsum[blockIdx.x] = s[1023];
}
__global__ void k_scan2(int nb) {
    __shared__ int s[128];
    int tid = threadIdx.x;
    int v = (tid < nb) ? g_bsum[tid] : 0;
    s[tid] = v;
    __syncthreads();
    #pragma unroll
    for (int off = 1; off < 128; off <<= 1) {
        int t = (tid >= off) ? s[tid - off] : 0;
        __syncthreads();
        s[tid] += t;
        __syncthreads();
    }
    if (tid < nb) g_boff[tid] = s[tid] - v;
}
__global__ void k_scan3(int n, int e) {
    int idx = blockIdx.x * 1024 + threadIdx.x;
    if (idx < n) {
        int o = g_off[idx] + g_boff[blockIdx.x];
        g_off[idx] = o;
        g_woff[idx] = o;
    }
    if (idx == 0) g_off[n] = e;
}
__global__ void k_scatter(const int* __restrict__ src, const int* __restrict__ dst, int e) {
    int i = blockIdx.x * blockDim.x + threadIdx.x;
    if (i < e) {
        int p = atomicAdd(&g_woff[dst[i]], 1);
        g_srcc[p] = src[i];
        g_pos[i] = p;
    }
}

// ---------------- fused conv: 2-phase (R3-proven) -----------------------------------
__global__ void k_conv(const float* __restrict__ bias, int which_ee, int n, int do_relu) {
    int gw   = (blockIdx.x * blockDim.x + threadIdx.x) >> 5;
    int lane = threadIdx.x & 31;
    if (gw >= n) return;
    const float* __restrict__ eec = which_ee ? g_eec2 : g_eec1;
    int beg = g_off[gw], end = g_off[gw + 1];
    float b0 = bias[lane], b1 = bias[lane + 32], b2 = bias[lane + 64];
    float out0, out1, out2;
    if (beg == end) {
        out0 = b0; out1 = b1; out2 = b2;
    } else {
        float4 er = g_er4[gw];
        // phase 1: edge-parallel logits -> exp -> store + per-lane sum
        float s0 = 0.f, s1 = 0.f, s2 = 0.f;
        for (int i = beg + lane; i < end; i += 32) {
            int sn = g_srcc[i];
            float4 el = g_el4[sn];
            size_t ip = (size_t)i * 3;
            float w0 = el.x + er.x + eec[ip + 0];
            float w1 = el.y + er.y + eec[ip + 1];
            float w2 = el.z + er.z + eec[ip + 2];
            w0 = (w0 > 0.f) ? w0 : 0.2f * w0;
            w1 = (w1 > 0.f) ? w1 : 0.2f * w1;
            w2 = (w2 > 0.f) ? w2 : 0.2f * w2;
            float x0 = __expf(w0), x1 = __expf(w1), x2 = __expf(w2);
            g_wc[ip + 0] = x0; g_wc[ip + 1] = x1; g_wc[ip + 2] = x2;
            s0 += x0; s1 += x1; s2 += x2;
        }
        #pragma unroll
        for (int o = 16; o; o >>= 1) {
            s0 += __shfl_xor_sync(0xffffffffu, s0, o);
            s1 += __shfl_xor_sync(0xffffffffu, s1, o);
            s2 += __shfl_xor_sync(0xffffffffu, s2, o);
        }
        __syncwarp();
        // phase 2: feature-parallel aggregation; unroll 8 for deeper MLP
        float a0 = 0.f, a1 = 0.f, a2 = 0.f;
        #pragma unroll 8
        for (int i = beg; i < end; i++) {
            int sn = g_srcc[i];
            size_t ip = (size_t)i * 3;
            float x0 = g_wc[ip + 0], x1 = g_wc[ip + 1], x2 = g_wc[ip + 2];
            const float* fr = g_ft + (size_t)sn * 96;
            a0 = fmaf(x0, fr[lane],      a0);
            a1 = fmaf(x1, fr[lane + 32], a1);
            a2 = fmaf(x2, fr[lane + 64], a2);
        }
        out0 = a0 / s0 + b0;
        out1 = a1 / s1 + b1;
        out2 = a2 / s2 + b2;
    }
    if (do_relu) {
        out0 = fmaxf(out0, 0.f); out1 = fmaxf(out1, 0.f); out2 = fmaxf(out2, 0.f);
    }
    float* o = g_h + (size_t)gw * 96;
    o[lane] = out0; o[lane + 32] = out1; o[lane + 64] = out2;
}

// ---------------- per-node P = h@Wp_top, Q = h@Wp_bot + bp ----------------
__global__ void k_pq(const float* __restrict__ Wp, const float* __restrict__ bp, int n) {
    __shared__ float sW[1920];
    __shared__ float sb[10];
    for (int i = threadIdx.x; i < 1920; i += blockDim.x) sW[i] = Wp[i];
    if (threadIdx.x < 10) sb[threadIdx.x] = bp[threadIdx.x];
    __syncthreads();
    int t = blockIdx.x * blockDim.x + threadIdx.x;
    if (t >= n * 10) return;
    int node = t / 10, c = t % 10;
    const float* hr = g_h + (size_t)node * 96;
    float p = 0.f, q = 0.f;
    #pragma unroll 4
    for (int j = 0; j < 96; j++) {
        float hv = hr[j];
        p = fmaf(hv, sW[j * 10 + c], p);
        q = fmaf(hv, sW[(96 + j) * 10 + c], q);
    }
    g_P[t] = p;
    g_Q[t] = q + sb[c];
}

// ---------------- score[e,:] = P[src] + Q[dst] ----------------
__global__ void k_score(const int* __restrict__ src, const int* __restrict__ dst,
                        float* __restrict__ out, int e) {
    __shared__ float sm[2560];
    int tid = threadIdx.x;
    int eb = blockIdx.x * 256;
    int ed = eb + tid;
    if (ed < e) {
        int sn = src[ed], dn = dst[ed];
        #pragma unroll
        for (int c = 0; c < 10; c++)
            sm[tid * 10 + c] = g_P[sn * 10 + c] + g_Q[dn * 10 + c];
    }
    __syncthreads();
    int cnt = (e - eb < 256 ? e - eb : 256) * 10;
    for (int i = tid; i < cnt; i += 256)
        out[(size_t)eb * 10 + i] = sm[i];
}

// ---------------- driver: two-stream DAG (graph-capture-legal fork/join) ----------
extern "C" void kernel_launch(void* const* d_in, const int* in_sizes, int n_in,
                              void* d_out, int out_size) {
    const float* nfeats = (const float*)d_in[0];
    const float* efeats = (const float*)d_in[1];
    const int*   src    = (const int*)  d_in[2];
    const int*   dst    = (const int*)  d_in[3];
    const float* W1  = (const float*)d_in[4];
    const float* We1 = (const float*)d_in[5];
    const float* al1 = (const float*)d_in[6];
    const float* ar1 = (const float*)d_in[7];
    const float* ae1 = (const float*)d_in[8];
    const float* b1  = (const float*)d_in[9];
    const float* W2  = (const float*)d_in[10];
    const float* We2 = (const float*)d_in[11];
    const float* al2 = (const float*)d_in[12];
    const float* ar2 = (const float*)d_in[13];
    const float* ae2 = (const float*)d_in[14];
    const float* b2  = (const float*)d_in[15];
    const float* Wp  = (const float*)d_in[16];
    const float* bp  = (const float*)d_in[17];
    float* out = (float*)d_out;

    int n = in_sizes[0] / 64;   // 100000
    int e = in_sizes[2];        // 1600000

    int eb   = (e + 255) / 256;
    int nb   = (n + 255) / 256;
    int nwb  = (n + 7) / 8;
    int nwb4 = (n + 31) / 32;
    int nb1k = (n + 1023) / 1024;

    // one-time infra (created on first call, outside any capture; reused thereafter)
    static cudaStream_t s1 = nullptr;
    static cudaEvent_t evFork = nullptr, evJoin = nullptr;
    if (s1 == nullptr) {
        cudaStreamCreateWithFlags(&s1, cudaStreamNonBlocking);
        cudaEventCreateWithFlags(&evFork, cudaEventDisableTiming);
        cudaEventCreateWithFlags(&evJoin, cudaEventDisableTiming);
    }

    // fork: side stream builds CSR + folded edge terms, main stream runs node GEMV
    cudaEventRecord(evFork, 0);
    cudaStreamWaitEvent(s1, evFork, 0);

    // side stream: CSR chain + ve + ee
    k_zero_deg<<<nb, 256, 0, s1>>>(n);
    k_deg<<<eb, 256, 0, s1>>>(dst, e);
    k_scan1<<<nb1k, 1024, 0, s1>>>(n);
    k_scan2<<<1, 128, 0, s1>>>(nb1k);
    k_scan3<<<nb1k, 1024, 0, s1>>>(n, e);
    k_scatter<<<eb, 256, 0, s1>>>(src, dst, e);
    k_ve<<<1, 192, 0, s1>>>(We1, ae1, We2, ae2);
    k_ee<<<eb, 256, 0, s1>>>(efeats, e);
    cudaEventRecord(evJoin, s1);

    // main stream: layer-1 node transform (independent of side chain)
    k_node4<64><<<nwb4, 256>>>(nfeats, W1, al1, ar1, n);

    // join, then the dependent tail
    cudaStreamWaitEvent(0, evJoin, 0);
    k_conv<<<nwb, 256>>>(b1, 0, n, 1);
    k_node4<96><<<nwb4, 256>>>(nullptr, W2, al2, ar2, n);
    k_conv<<<nwb, 256>>>(b2, 1, n, 0);
    k_pq<<<(n * 10 + 255) / 256, 256>>>(Wp, bp, n);
    k_score<<<eb, 256>>>(src, dst, out, e);
}

// round 8
// speedup vs baseline: 1.5166x; 1.0297x over previous
#include <cuda_runtime.h>
#include <math.h>

#define MAXN 100000
#define MAXE 1600000
typedef unsigned long long u64;

// ---------------- scratch ----------------
__device__ float  g_ft[MAXN * 96];
__device__ float  g_h [MAXN * 96];
__device__ float4 g_el4[MAXN];
__device__ float4 g_er4[MAXN];
__device__ float4 g_eec24[MAXE];     // layer-2 ee terms, CSR order
__device__ float4 g_wc4[MAXE];       // exp weights (x0,x1,x2,0), CSR order, reused per layer
__device__ int    g_srcc[MAXE];      // src per CSR slot
__device__ int    g_dstc[MAXE];      // dst per CSR slot
__device__ int    g_pos [MAXE];      // edge -> CSR slot
__device__ int    g_deg [MAXN];
__device__ int    g_off [MAXN + 1];
__device__ int    g_woff[MAXN];
__device__ int    g_bsum[128];
__device__ int    g_boff[128];
__device__ float  g_P[MAXN * 10];
__device__ float  g_Q[MAXN * 10];
__device__ float  g_Ve[2][32][3];

__device__ __forceinline__ void ffma2(u64& acc, u64 v, u64 w) {
    asm("fma.rn.f32x2 %0, %1, %2, %0;" : "+l"(acc) : "l"(v), "l"(w));
}
__device__ __forceinline__ float unpack_sum(u64 a) {
    unsigned lo, hi;
    asm("mov.b64 {%0, %1}, %2;" : "=r"(lo), "=r"(hi) : "l"(a));
    return __uint_as_float(lo) + __uint_as_float(hi);
}
__device__ __forceinline__ float leaky(float w) { return (w > 0.f) ? w : 0.2f * w; }

// ---------------- K0: fold We @ ae for both layers ----------------
__global__ void k_ve(const float* __restrict__ We1, const float* __restrict__ ae1,
                     const float* __restrict__ We2, const float* __restrict__ ae2) {
    int t = threadIdx.x;
    if (t >= 192) return;
    int c = t / 96, r = t % 96, d = r / 3, h = r % 3;
    const float* We = c ? We2 : We1;
    const float* ae = c ? ae2 : ae1;
    float s = 0.f;
    #pragma unroll
    for (int f = 0; f < 32; f++) s = fmaf(We[d * 96 + h * 32 + f], ae[h * 32 + f], s);
    g_Ve[c][d][h] = s;
}

// ---------------- node transform: 4 nodes/warp, FFMA2 packed along k ----------------
template <int K>
__global__ void k_node4(const float* __restrict__ in,   // nullptr => read g_h
                        const float* __restrict__ W,
                        const float* __restrict__ al, const float* __restrict__ ar,
                        int n) {
    constexpr int KP = K + 2;
    __shared__ float sWT[96 * KP];
    __shared__ float sal[96], sar[96];
    for (int idx = threadIdx.x; idx < K * 96; idx += blockDim.x) {
        int k = idx / 96, c = idx % 96;
        sWT[c * KP + k] = W[idx];
    }
    if (threadIdx.x < 96) { sal[threadIdx.x] = al[threadIdx.x]; sar[threadIdx.x] = ar[threadIdx.x]; }
    __syncthreads();

    int warp = (blockIdx.x * blockDim.x + threadIdx.x) >> 5;
    int lane = threadIdx.x & 31;
    int nb = warp * 4;
    if (nb >= n) return;
    const float* base = in ? in : g_h;

    const u64* row[4];
    #pragma unroll
    for (int m = 0; m < 4; m++) {
        int node = nb + m < n ? nb + m : n - 1;
        row[m] = (const u64*)(base + (size_t)node * K);
    }
    const u64* w0p = (const u64*)(sWT + (size_t)lane * KP);
    const u64* w1p = (const u64*)(sWT + (size_t)(lane + 32) * KP);
    const u64* w2p = (const u64*)(sWT + (size_t)(lane + 64) * KP);

    u64 acc[4][3];
    #pragma unroll
    for (int m = 0; m < 4; m++) { acc[m][0] = 0ull; acc[m][1] = 0ull; acc[m][2] = 0ull; }

    #pragma unroll 4
    for (int kp = 0; kp < K / 2; kp++) {
        u64 w0 = w0p[kp], w1 = w1p[kp], w2 = w2p[kp];
        u64 v0 = row[0][kp], v1 = row[1][kp], v2 = row[2][kp], v3 = row[3][kp];
        ffma2(acc[0][0], v0, w0); ffma2(acc[0][1], v0, w1); ffma2(acc[0][2], v0, w2);
        ffma2(acc[1][0], v1, w0); ffma2(acc[1][1], v1, w1); ffma2(acc[1][2], v1, w2);
        ffma2(acc[2][0], v2, w0); ffma2(acc[2][1], v2, w1); ffma2(acc[2][2], v2, w2);
        ffma2(acc[3][0], v3, w0); ffma2(acc[3][1], v3, w1); ffma2(acc[3][2], v3, w2);
    }

    #pragma unroll
    for (int m = 0; m < 4; m++) {
        int node = nb + m;
        if (node >= n) break;
        float a0 = unpack_sum(acc[m][0]);
        float a1 = unpack_sum(acc[m][1]);
        float a2 = unpack_sum(acc[m][2]);
        float* fo = g_ft + (size_t)node * 96;
        fo[lane] = a0; fo[lane + 32] = a1; fo[lane + 64] = a2;
        float e0 = a0 * sal[lane], e1 = a1 * sal[lane + 32], e2 = a2 * sal[lane + 64];
        float r0 = a0 * sar[lane], r1 = a1 * sar[lane + 32], r2 = a2 * sar[lane + 64];
        #pragma unroll
        for (int o = 16; o; o >>= 1) {
            e0 += __shfl_xor_sync(0xffffffffu, e0, o);
            e1 += __shfl_xor_sync(0xffffffffu, e1, o);
            e2 += __shfl_xor_sync(0xffffffffu, e2, o);
            r0 += __shfl_xor_sync(0xffffffffu, r0, o);
            r1 += __shfl_xor_sync(0xffffffffu, r1, o);
            r2 += __shfl_xor_sync(0xffffffffu, r2, o);
        }
        if (lane == 0) {
            g_el4[node] = make_float4(e0, e1, e2, 0.f);
            g_er4[node] = make_float4(r0, r1, r2, 0.f);
        }
    }
}

// ---------------- fused ee: edge-parallel; layer-1 exp weights + layer-2 ee terms ---
__global__ void k_ee_fused(const float* __restrict__ ef,
                           const int* __restrict__ src, const int* __restrict__ dst,
                           int e_cnt) {
    __shared__ float sVe[192];
    if (threadIdx.x < 192) sVe[threadIdx.x] = ((const float*)g_Ve)[threadIdx.x];
    __syncthreads();
    int e = blockIdx.x * blockDim.x + threadIdx.x;
    if (e >= e_cnt) return;
    const float4* p = (const float4*)(ef + (size_t)e * 32);
    float acc0 = 0, acc1 = 0, acc2 = 0, acc3 = 0, acc4 = 0, acc5 = 0;
    #pragma unroll
    for (int q = 0; q < 8; q++) {
        float4 v = p[q];
        float xs[4] = {v.x, v.y, v.z, v.w};
        #pragma unroll
        for (int j = 0; j < 4; j++) {
            int d = q * 4 + j;
            float x = xs[j];
            acc0 = fmaf(x, sVe[d * 3 + 0],      acc0);
            acc1 = fmaf(x, sVe[d * 3 + 1],      acc1);
            acc2 = fmaf(x, sVe[d * 3 + 2],      acc2);
            acc3 = fmaf(x, sVe[96 + d * 3 + 0], acc3);
            acc4 = fmaf(x, sVe[96 + d * 3 + 1], acc4);
            acc5 = fmaf(x, sVe[96 + d * 3 + 2], acc5);
        }
    }
    int sn = src[e], dn = dst[e];
    float4 el = g_el4[sn];
    float4 er = g_er4[dn];
    float x0 = __expf(leaky(el.x + er.x + acc0));
    float x1 = __expf(leaky(el.y + er.y + acc1));
    float x2 = __expf(leaky(el.z + er.z + acc2));
    int pp = g_pos[e];
    g_wc4[pp]   = make_float4(x0, x1, x2, 0.f);
    g_eec24[pp] = make_float4(acc3, acc4, acc5, 0.f);
}

// ---------------- layer-2 exp weights: edge-parallel over CSR slots ----------------
__global__ void k_wc2(int e_cnt) {
    int i = blockIdx.x * blockDim.x + threadIdx.x;
    if (i >= e_cnt) return;
    int sn = g_srcc[i], dn = g_dstc[i];
    float4 el = g_el4[sn];
    float4 er = g_er4[dn];
    float4 ee = g_eec24[i];
    float x0 = __expf(leaky(el.x + er.x + ee.x));
    float x1 = __expf(leaky(el.y + er.y + ee.y));
    float x2 = __expf(leaky(el.z + er.z + ee.z));
    g_wc4[i] = make_float4(x0, x1, x2, 0.f);
}

// ---------------- CSR build ----------------
__global__ void k_zero_deg(int n) {
    int i = blockIdx.x * blockDim.x + threadIdx.x;
    if (i < n) g_deg[i] = 0;
}
__global__ void k_deg(const int* __restrict__ dst, int e) {
    int i = blockIdx.x * blockDim.x + threadIdx.x;
    if (i < e) atomicAdd(&g_deg[dst[i]], 1);
}
__global__ void k_scan1(int n) {
    __shared__ int s[1024];
    int idx = blockIdx.x * 1024 + threadIdx.x;
    int v = (idx < n) ? g_deg[idx] : 0;
    s[threadIdx.x] = v;
    __syncthreads();
    #pragma unroll
    for (int off = 1; off < 1024; off <<= 1) {
        int t = (threadIdx.x >= off) ? s[threadIdx.x - off] : 0;
        __syncthreads();
        s[threadIdx.x] += t;
        __syncthreads();
    }
    if (idx < n) g_off[idx] = s[threadIdx.x] - v;
    if (threadIdx.x == 1023) g_bsum[blockIdx.x] = s[1023];
}
__global__ void k_scan2(int nb) {
    __shared__ int s[128];
    int tid = threadIdx.x;
    int v = (tid < nb) ? g_bsum[tid] : 0;
    s[tid] = v;
    __syncthreads();
    #pragma unroll
    for (int off = 1; off < 128; off <<= 1) {
        int t = (tid >= off) ? s[tid - off] : 0;
        __syncthreads();
        s[tid] += t;
        __syncthreads();
    }
    if (tid < nb) g_boff[tid] = s[tid] - v;
}
__global__ void k_scan3(int n, int e) {
    int idx = blockIdx.x * 1024 + threadIdx.x;
    if (idx < n) {
        int o = g_off[idx] + g_boff[blockIdx.x];
        g_off[idx] = o;
        g_woff[idx] = o;
    }
    if (idx == 0) g_off[n] = e;
}
__global__ void k_scatter(const int* __restrict__ src, const int* __restrict__ dst, int e) {
    int i = blockIdx.x * blockDim.x + threadIdx.x;
    if (i < e) {
        int d = dst[i];
        int p = atomicAdd(&g_woff[d], 1);
        g_srcc[p] = src[i];
        g_dstc[p] = d;
        g_pos[i] = p;
    }
}

// ---------------- conv: single sweep (denominator folded into aggregation) ---------
// One warp per dst node; per edge: 1 uniform LDG.128 (weights) + 3 independent gathers.
__global__ void k_conv(const float* __restrict__ bias, int n, int do_relu) {
    int gw   = (blockIdx.x * blockDim.x + threadIdx.x) >> 5;
    int lane = threadIdx.x & 31;
    if (gw >= n) return;
    int beg = g_off[gw], end = g_off[gw + 1];
    float b0 = bias[lane], b1 = bias[lane + 32], b2 = bias[lane + 64];
    float out0, out1, out2;
    if (beg == end) {
        out0 = b0; out1 = b1; out2 = b2;
    } else {
        float s0 = 0.f, s1 = 0.f, s2 = 0.f;
        float a0 = 0.f, a1 = 0.f, a2 = 0.f;
        #pragma unroll 8
        for (int i = beg; i < end; i++) {
            float4 x = g_wc4[i];                    // warp-uniform
            int sn = g_srcc[i];                     // warp-uniform
            const float* fr = g_ft + (size_t)sn * 96;
            a0 = fmaf(x.x, fr[lane],      a0);
            a1 = fmaf(x.y, fr[lane + 32], a1);
            a2 = fmaf(x.z, fr[lane + 64], a2);
            s0 += x.x; s1 += x.y; s2 += x.z;
        }
        out0 = a0 / s0 + b0;
        out1 = a1 / s1 + b1;
        out2 = a2 / s2 + b2;
    }
    if (do_relu) {
        out0 = fmaxf(out0, 0.f); out1 = fmaxf(out1, 0.f); out2 = fmaxf(out2, 0.f);
    }
    float* o = g_h + (size_t)gw * 96;
    o[lane] = out0; o[lane + 32] = out1; o[lane + 64] = out2;
}

// ---------------- per-node P = h@Wp_top, Q = h@Wp_bot + bp ----------------
__global__ void k_pq(const float* __restrict__ Wp, const float* __restrict__ bp, int n) {
    __shared__ float sW[1920];
    __shared__ float sb[10];
    for (int i = threadIdx.x; i < 1920; i += blockDim.x) sW[i] = Wp[i];
    if (threadIdx.x < 10) sb[threadIdx.x] = bp[threadIdx.x];
    __syncthreads();
    int t = blockIdx.x * blockDim.x + threadIdx.x;
    if (t >= n * 10) return;
    int node = t / 10, c = t % 10;
    const float* hr = g_h + (size_t)node * 96;
    float p = 0.f, q = 0.f;
    #pragma unroll 4
    for (int j = 0; j < 96; j++) {
        float hv = hr[j];
        p = fmaf(hv, sW[j * 10 + c], p);
        q = fmaf(hv, sW[(96 + j) * 10 + c], q);
    }
    g_P[t] = p;
    g_Q[t] = q + sb[c];
}

// ---------------- score[e,:] = P[src] + Q[dst] ----------------
__global__ void k_score(const int* __restrict__ src, const int* __restrict__ dst,
                        float* __restrict__ out, int e) {
    __shared__ float sm[2560];
    int tid = threadIdx.x;
    int eb = blockIdx.x * 256;
    int ed = eb + tid;
    if (ed < e) {
        int sn = src[ed], dn = dst[ed];
        #pragma unroll
        for (int c = 0; c < 10; c++)
            sm[tid * 10 + c] = g_P[sn * 10 + c] + g_Q[dn * 10 + c];
    }
    __syncthreads();
    int cnt = (e - eb < 256 ? e - eb : 256) * 10;
    for (int i = tid; i < cnt; i += 256)
        out[(size_t)eb * 10 + i] = sm[i];
}

// ---------------- driver: two-stream DAG ----------------
extern "C" void kernel_launch(void* const* d_in, const int* in_sizes, int n_in,
                              void* d_out, int out_size) {
    const float* nfeats = (const float*)d_in[0];
    const float* efeats = (const float*)d_in[1];
    const int*   src    = (const int*)  d_in[2];
    const int*   dst    = (const int*)  d_in[3];
    const float* W1  = (const float*)d_in[4];
    const float* We1 = (const float*)d_in[5];
    const float* al1 = (const float*)d_in[6];
    const float* ar1 = (const float*)d_in[7];
    const float* ae1 = (const float*)d_in[8];
    const float* b1  = (const float*)d_in[9];
    const float* W2  = (const float*)d_in[10];
    const float* We2 = (const float*)d_in[11];
    const float* al2 = (const float*)d_in[12];
    const float* ar2 = (const float*)d_in[13];
    const float* ae2 = (const float*)d_in[14];
    const float* b2  = (const float*)d_in[15];
    const float* Wp  = (const float*)d_in[16];
    const float* bp  = (const float*)d_in[17];
    float* out = (float*)d_out;

    int n = in_sizes[0] / 64;   // 100000
    int e = in_sizes[2];        // 1600000

    int eb   = (e + 255) / 256;
    int nb   = (n + 255) / 256;
    int nwb  = (n + 7) / 8;
    int nwb4 = (n + 31) / 32;
    int nb1k = (n + 1023) / 1024;

    static cudaStream_t s1 = nullptr;
    static cudaEvent_t evFork = nullptr, evJoin = nullptr;
    if (s1 == nullptr) {
        cudaStreamCreateWithFlags(&s1, cudaStreamNonBlocking);
        cudaEventCreateWithFlags(&evFork, cudaEventDisableTiming);
        cudaEventCreateWithFlags(&evJoin, cudaEventDisableTiming);
    }

    // fork: side stream = CSR build; main stream = ve + layer-1 node transform
    cudaEventRecord(evFork, 0);
    cudaStreamWaitEvent(s1, evFork, 0);

    k_zero_deg<<<nb, 256, 0, s1>>>(n);
    k_deg<<<eb, 256, 0, s1>>>(dst, e);
    k_ve<<<1, 192>>>(We1, ae1, We2, ae2);
    k_node4<64><<<nwb4, 256>>>(nfeats, W1, al1, ar1, n);
    k_scan1<<<nb1k, 1024, 0, s1>>>(n);
    k_scan2<<<1, 128, 0, s1>>>(nb1k);
    k_scan3<<<nb1k, 1024, 0, s1>>>(n, e);
    k_scatter<<<eb, 256, 0, s1>>>(src, dst, e);
    cudaEventRecord(evJoin, s1);
    cudaStreamWaitEvent(0, evJoin, 0);

    // layer 1: fused edge kernel (ee1->exp weights, ee2 terms), then slim conv
    k_ee_fused<<<eb, 256>>>(efeats, src, dst, e);
    k_conv<<<nwb, 256>>>(b1, n, 1);

    // layer 2
    k_node4<96><<<nwb4, 256>>>(nullptr, W2, al2, ar2, n);
    k_wc2<<<eb, 256>>>(e);
    k_conv<<<nwb, 256>>>(b2, n, 0);

    // edge score head
    k_pq<<<(n * 10 + 255) / 256, 256>>>(Wp, bp, n);
    k_score<<<eb, 256>>>(src, dst, out, e);
}

// round 9
// speedup vs baseline: 1.7530x; 1.1559x over previous
#include <cuda_runtime.h>
#include <cuda_fp16.h>
#include <mma.h>
#include <math.h>

#define MAXN 100000
#define MAXE 1600000
typedef unsigned long long u64;
using namespace nvcuda;

// ---------------- scratch ----------------
__device__ float  g_ft[MAXN * 96];
__device__ float  g_h [MAXN * 96];
__device__ float4 g_el4[MAXN];
__device__ float4 g_er4[MAXN];
__device__ float4 g_eec24[MAXE];     // layer-2 ee terms, CSR order
__device__ float4 g_wc4[MAXE];       // exp weights (x0,x1,x2,0), CSR order
__device__ int    g_srcc[MAXE];
__device__ int    g_dstc[MAXE];
__device__ int    g_pos [MAXE];
__device__ int    g_deg [MAXN];
__device__ int    g_off [MAXN + 1];
__device__ int    g_woff[MAXN];
__device__ int    g_bsum[128];
__device__ int    g_boff[128];
__device__ float  g_P[MAXN * 10];
__device__ float  g_Q[MAXN * 10];
__device__ float  g_Ve[2][32][3];

__device__ __forceinline__ float leaky(float w) { return (w > 0.f) ? w : 0.2f * w; }

// ---------------- K0: fold We @ ae for both layers ----------------
__global__ void k_ve(const float* __restrict__ We1, const float* __restrict__ ae1,
                     const float* __restrict__ We2, const float* __restrict__ ae2) {
    int t = threadIdx.x;
    if (t >= 192) return;
    int c = t / 96, r = t % 96, d = r / 3, h = r % 3;
    const float* We = c ? We2 : We1;
    const float* ae = c ? ae2 : ae1;
    float s = 0.f;
    #pragma unroll
    for (int f = 0; f < 32; f++) s = fmaf(We[d * 96 + h * 32 + f], ae[h * 32 + f], s);
    g_Ve[c][d][h] = s;
}

// ---------------- node transform: wmma fp16 GEMM (fp32 accum) ----------------------
// Block tile C[64 x 96]; 256 threads = 8 warps; warp -> 1 M-tile x 3 N-tiles.
// Epilogue (fp32): ft store + el/er head reductions.
template <int K>
__global__ void __launch_bounds__(256)
k_wgemm(const float* __restrict__ in,    // nullptr => read g_h
        const float* __restrict__ W,
        const float* __restrict__ al, const float* __restrict__ ar,
        int n) {
    constexpr int AP = K + 8;                    // half elems per A row (pad, mult of 8)
    constexpr int ABYTES = 64 * AP * 2;
    constexpr int BBYTES = K * 96 * 2;
    constexpr int OBYTES = 64 * 100 * 4;
    constexpr int SBYTES = (ABYTES + BBYTES > OBYTES) ? (ABYTES + BBYTES) : OBYTES;
    __shared__ __align__(16) char raw[SBYTES];
    __half* sA = (__half*)raw;                   // [64][AP]
    __half* sB = (__half*)(raw + ABYTES);        // [K][96]
    float*  Os = (float*)raw;                    // [64][100] (overlays after compute)
    __shared__ float sal[96], sar[96];

    int tid = threadIdx.x;
    if (tid < 96) { sal[tid] = al[tid]; sar[tid] = ar[tid]; }

    int nb = blockIdx.x * 64;
    const float* base = in ? in : g_h;

    // stage A (fp32 -> fp16), coalesced float4 reads
    for (int i = tid; i < 64 * (K / 4); i += 256) {
        int row = i / (K / 4), kq = i % (K / 4);
        int gr = nb + row; if (gr >= n) gr = n - 1;
        float4 v = ((const float4*)(base + (size_t)gr * K))[kq];
        __half* d = sA + row * AP + kq * 4;
        d[0] = __float2half(v.x); d[1] = __float2half(v.y);
        d[2] = __float2half(v.z); d[3] = __float2half(v.w);
    }
    // stage W (fp32 -> fp16)
    for (int i = tid; i < K * 24; i += 256) {
        float4 v = ((const float4*)W)[i];
        __half* d = sB + i * 4;
        d[0] = __float2half(v.x); d[1] = __float2half(v.y);
        d[2] = __float2half(v.z); d[3] = __float2half(v.w);
    }
    __syncthreads();

    int wid = tid >> 5;
    int mt  = wid & 3;                 // M tile 0..3
    int ng  = (wid >> 2) * 3;          // N tiles ng..ng+2

    wmma::fragment<wmma::accumulator, 16, 16, 16, float> c[3];
    #pragma unroll
    for (int j = 0; j < 3; j++) wmma::fill_fragment(c[j], 0.f);

    #pragma unroll
    for (int kt = 0; kt < K / 16; kt++) {
        wmma::fragment<wmma::matrix_a, 16, 16, 16, __half, wmma::row_major> a;
        wmma::load_matrix_sync(a, sA + mt * 16 * AP + kt * 16, AP);
        #pragma unroll
        for (int j = 0; j < 3; j++) {
            wmma::fragment<wmma::matrix_b, 16, 16, 16, __half, wmma::row_major> b;
            wmma::load_matrix_sync(b, sB + kt * 16 * 96 + (ng + j) * 16, 96);
            wmma::mma_sync(c[j], a, b, c[j]);
        }
    }
    __syncthreads();   // done reading sA/sB; reuse as Os

    #pragma unroll
    for (int j = 0; j < 3; j++)
        wmma::store_matrix_sync(Os + mt * 16 * 100 + (ng + j) * 16, c[j], 100, wmma::mem_row_major);
    __syncthreads();

    // ft store (fp32)
    for (int i = tid; i < 64 * 32; i += 256) {
        int nl = i >> 5, j0 = i & 31;
        int node = nb + nl;
        if (node < n) {
            const float* orow = Os + nl * 100;
            float* fo = g_ft + (size_t)node * 96;
            fo[j0]      = orow[j0];
            fo[j0 + 32] = orow[j0 + 32];
            fo[j0 + 64] = orow[j0 + 64];
        }
    }
    // el/er: 64 threads, one node each
    if (tid < 64 && nb + tid < n) {
        const float4* orow = (const float4*)(Os + tid * 100);
        float el[3] = {0.f, 0.f, 0.f}, er[3] = {0.f, 0.f, 0.f};
        #pragma unroll
        for (int q = 0; q < 24; q++) {
            float4 v = orow[q];
            float xs[4] = {v.x, v.y, v.z, v.w};
            #pragma unroll
            for (int j = 0; j < 4; j++) {
                int cix = q * 4 + j, h = cix >> 5;
                el[h] = fmaf(xs[j], sal[cix], el[h]);
                er[h] = fmaf(xs[j], sar[cix], er[h]);
            }
        }
        g_el4[nb + tid] = make_float4(el[0], el[1], el[2], 0.f);
        g_er4[nb + tid] = make_float4(er[0], er[1], er[2], 0.f);
    }
}

// ---------------- fused ee: edge-parallel; layer-1 exp weights + layer-2 ee terms ---
__global__ void k_ee_fused(const float* __restrict__ ef,
                           const int* __restrict__ src, const int* __restrict__ dst,
                           int e_cnt) {
    __shared__ float sVe[192];
    if (threadIdx.x < 192) sVe[threadIdx.x] = ((const float*)g_Ve)[threadIdx.x];
    __syncthreads();
    int e = blockIdx.x * blockDim.x + threadIdx.x;
    if (e >= e_cnt) return;
    const float4* p = (const float4*)(ef + (size_t)e * 32);
    float acc0 = 0, acc1 = 0, acc2 = 0, acc3 = 0, acc4 = 0, acc5 = 0;
    #pragma unroll
    for (int q = 0; q < 8; q++) {
        float4 v = p[q];
        float xs[4] = {v.x, v.y, v.z, v.w};
        #pragma unroll
        for (int j = 0; j < 4; j++) {
            int d = q * 4 + j;
            float x = xs[j];
            acc0 = fmaf(x, sVe[d * 3 + 0],      acc0);
            acc1 = fmaf(x, sVe[d * 3 + 1],      acc1);
            acc2 = fmaf(x, sVe[d * 3 + 2],      acc2);
            acc3 = fmaf(x, sVe[96 + d * 3 + 0], acc3);
            acc4 = fmaf(x, sVe[96 + d * 3 + 1], acc4);
            acc5 = fmaf(x, sVe[96 + d * 3 + 2], acc5);
        }
    }
    int sn = src[e], dn = dst[e];
    float4 el = g_el4[sn];
    float4 er = g_er4[dn];
    float x0 = __expf(leaky(el.x + er.x + acc0));
    float x1 = __expf(leaky(el.y + er.y + acc1));
    float x2 = __expf(leaky(el.z + er.z + acc2));
    int pp = g_pos[e];
    g_wc4[pp]   = make_float4(x0, x1, x2, 0.f);
    g_eec24[pp] = make_float4(acc3, acc4, acc5, 0.f);
}

// ---------------- layer-2 exp weights: edge-parallel over CSR slots ----------------
__global__ void k_wc2(int e_cnt) {
    int i = blockIdx.x * blockDim.x + threadIdx.x;
    if (i >= e_cnt) return;
    int sn = g_srcc[i], dn = g_dstc[i];
    float4 el = g_el4[sn];
    float4 er = g_er4[dn];
    float4 ee = g_eec24[i];
    float x0 = __expf(leaky(el.x + er.x + ee.x));
    float x1 = __expf(leaky(el.y + er.y + ee.y));
    float x2 = __expf(leaky(el.z + er.z + ee.z));
    g_wc4[i] = make_float4(x0, x1, x2, 0.f);
}

// ---------------- CSR build ----------------
__global__ void k_zero_deg(int n) {
    int i = blockIdx.x * blockDim.x + threadIdx.x;
    if (i < n) g_deg[i] = 0;
}
__global__ void k_deg(const int* __restrict__ dst, int e) {
    int i = blockIdx.x * blockDim.x + threadIdx.x;
    if (i < e) atomicAdd(&g_deg[dst[i]], 1);
}
__global__ void k_scan1(int n) {
    __shared__ int s[1024];
    int idx = blockIdx.x * 1024 + threadIdx.x;
    int v = (idx < n) ? g_deg[idx] : 0;
    s[threadIdx.x] = v;
    __syncthreads();
    #pragma unroll
    for (int off = 1; off < 1024; off <<= 1) {
        int t = (threadIdx.x >= off) ? s[threadIdx.x - off] : 0;
        __syncthreads();
        s[threadIdx.x] += t;
        __syncthreads();
    }
    if (idx < n) g_off[idx] = s[threadIdx.x] - v;
    if (threadIdx.x == 1023) g_bsum[blockIdx.x] = s[1023];
}
__global__ void k_scan2(int nb) {
    __shared__ int s[128];
    int tid = threadIdx.x;
    int v = (tid < nb) ? g_bsum[tid] : 0;
    s[tid] = v;
    __syncthreads();
    #pragma unroll
    for (int off = 1; off < 128; off <<= 1) {
        int t = (tid >= off) ? s[tid - off] : 0;
        __syncthreads();
        s[tid] += t;
        __syncthreads();
    }
    if (tid < nb) g_boff[tid] = s[tid] - v;
}
__global__ void k_scan3(int n, int e) {
    int idx = blockIdx.x * 1024 + threadIdx.x;
    if (idx < n) {
        int o = g_off[idx] + g_boff[blockIdx.x];
        g_off[idx] = o;
        g_woff[idx] = o;
    }
    if (idx == 0) g_off[n] = e;
}
__global__ void k_scatter(const int* __restrict__ src, const int* __restrict__ dst, int e) {
    int i = blockIdx.x * blockDim.x + threadIdx.x;
    if (i < e) {
        int d = dst[i];
        int p = atomicAdd(&g_woff[d], 1);
        g_srcc[p] = src[i];
        g_dstc[p] = d;
        g_pos[i] = p;
    }
}

// ---------------- conv: single sweep (denominator folded into aggregation) ---------
__global__ void k_conv(const float* __restrict__ bias, int n, int do_relu) {
    int gw   = (blockIdx.x * blockDim.x + threadIdx.x) >> 5;
    int lane = threadIdx.x & 31;
    if (gw >= n) return;
    int beg = g_off[gw], end = g_off[gw + 1];
    float b0 = bias[lane], b1 = bias[lane + 32], b2 = bias[lane + 64];
    float out0, out1, out2;
    if (beg == end) {
        out0 = b0; out1 = b1; out2 = b2;
    } else {
        float s0 = 0.f, s1 = 0.f, s2 = 0.f;
        float a0 = 0.f, a1 = 0.f, a2 = 0.f;
        #pragma unroll 8
        for (int i = beg; i < end; i++) {
            float4 x = g_wc4[i];
            int sn = g_srcc[i];
            const float* fr = g_ft + (size_t)sn * 96;
            a0 = fmaf(x.x, fr[lane],      a0);
            a1 = fmaf(x.y, fr[lane + 32], a1);
            a2 = fmaf(x.z, fr[lane + 64], a2);
            s0 += x.x; s1 += x.y; s2 += x.z;
        }
        out0 = a0 / s0 + b0;
        out1 = a1 / s1 + b1;
        out2 = a2 / s2 + b2;
    }
    if (do_relu) {
        out0 = fmaxf(out0, 0.f); out1 = fmaxf(out1, 0.f); out2 = fmaxf(out2, 0.f);
    }
    float* o = g_h + (size_t)gw * 96;
    o[lane] = out0; o[lane + 32] = out1; o[lane + 64] = out2;
}

// ---------------- per-node P = h@Wp_top, Q = h@Wp_bot + bp ----------------
__global__ void k_pq(const float* __restrict__ Wp, const float* __restrict__ bp, int n) {
    __shared__ float sW[1920];
    __shared__ float sb[10];
    for (int i = threadIdx.x; i < 1920; i += blockDim.x) sW[i] = Wp[i];
    if (threadIdx.x < 10) sb[threadIdx.x] = bp[threadIdx.x];
    __syncthreads();
    int t = blockIdx.x * blockDim.x + threadIdx.x;
    if (t >= n * 10) return;
    int node = t / 10, c = t % 10;
    const float* hr = g_h + (size_t)node * 96;
    float p = 0.f, q = 0.f;
    #pragma unroll 4
    for (int j = 0; j < 96; j++) {
        float hv = hr[j];
        p = fmaf(hv, sW[j * 10 + c], p);
        q = fmaf(hv, sW[(96 + j) * 10 + c], q);
    }
    g_P[t] = p;
    g_Q[t] = q + sb[c];
}

// ---------------- score[e,:] = P[src] + Q[dst] ----------------
__global__ void k_score(const int* __restrict__ src, const int* __restrict__ dst,
                        float* __restrict__ out, int e) {
    __shared__ float sm[2560];
    int tid = threadIdx.x;
    int eb = blockIdx.x * 256;
    int ed = eb + tid;
    if (ed < e) {
        int sn = src[ed], dn = dst[ed];
        #pragma unroll
        for (int c = 0; c < 10; c++)
            sm[tid * 10 + c] = g_P[sn * 10 + c] + g_Q[dn * 10 + c];
    }
    __syncthreads();
    int cnt = (e - eb < 256 ? e - eb : 256) * 10;
    for (int i = tid; i < cnt; i += 256)
        out[(size_t)eb * 10 + i] = sm[i];
}

// ---------------- driver: two-stream DAG ----------------
extern "C" void kernel_launch(void* const* d_in, const int* in_sizes, int n_in,
                              void* d_out, int out_size) {
    const float* nfeats = (const float*)d_in[0];
    const float* efeats = (const float*)d_in[1];
    const int*   src    = (const int*)  d_in[2];
    const int*   dst    = (const int*)  d_in[3];
    const float* W1  = (const float*)d_in[4];
    const float* We1 = (const float*)d_in[5];
    const float* al1 = (const float*)d_in[6];
    const float* ar1 = (const float*)d_in[7];
    const float* ae1 = (const float*)d_in[8];
    const float* b1  = (const float*)d_in[9];
    const float* W2  = (const float*)d_in[10];
    const float* We2 = (const float*)d_in[11];
    const float* al2 = (const float*)d_in[12];
    const float* ar2 = (const float*)d_in[13];
    const float* ae2 = (const float*)d_in[14];
    const float* b2  = (const float*)d_in[15];
    const float* Wp  = (const float*)d_in[16];
    const float* bp  = (const float*)d_in[17];
    float* out = (float*)d_out;

    int n = in_sizes[0] / 64;   // 100000
    int e = in_sizes[2];        // 1600000

    int eb   = (e + 255) / 256;
    int nb   = (n + 255) / 256;
    int nwb  = (n + 7) / 8;
    int ngb  = (n + 63) / 64;
    int nb1k = (n + 1023) / 1024;

    static cudaStream_t s1 = nullptr;
    static cudaEvent_t evFork = nullptr, evJoin = nullptr;
    if (s1 == nullptr) {
        cudaStreamCreateWithFlags(&s1, cudaStreamNonBlocking);
        cudaEventCreateWithFlags(&evFork, cudaEventDisableTiming);
        cudaEventCreateWithFlags(&evJoin, cudaEventDisableTiming);
    }

    // fork: side stream = CSR build; main stream = ve + layer-1 node transform
    cudaEventRecord(evFork, 0);
    cudaStreamWaitEvent(s1, evFork, 0);

    k_zero_deg<<<nb, 256, 0, s1>>>(n);
    k_deg<<<eb, 256, 0, s1>>>(dst, e);
    k_ve<<<1, 192>>>(We1, ae1, We2, ae2);
    k_wgemm<64><<<ngb, 256>>>(nfeats, W1, al1, ar1, n);
    k_scan1<<<nb1k, 1024, 0, s1>>>(n);
    k_scan2<<<1, 128, 0, s1>>>(nb1k);
    k_scan3<<<nb1k, 1024, 0, s1>>>(n, e);
    k_scatter<<<eb, 256, 0, s1>>>(src, dst, e);
    cudaEventRecord(evJoin, s1);
    cudaStreamWaitEvent(0, evJoin, 0);

    // layer 1
    k_ee_fused<<<eb, 256>>>(efeats, src, dst, e);
    k_conv<<<nwb, 256>>>(b1, n, 1);

    // layer 2
    k_wgemm<96><<<ngb, 256>>>(nullptr, W2, al2, ar2, n);
    k_wc2<<<eb, 256>>>(e);
    k_conv<<<nwb, 256>>>(b2, n, 0);

    // edge score head
    k_pq<<<(n * 10 + 255) / 256, 256>>>(Wp, bp, n);
    k_score<<<eb, 256>>>(src, dst, out, e);
}